// round 6
// baseline (speedup 1.0000x reference)
#include <cuda_runtime.h>

// Cox partial-likelihood loss, n = 8192.
// loss = -mean_i[ (theta_i - log(sum_{j: t_j>=t_i} exp(theta_j) + eps)) * e_i ]
//
// Phase A: g_exp[j] = exp(risk[j])
// Phase B: tiled O(n^2) predicated accumulation -> per-(i, j-chunk) partials
// Phase C: reduce partials per i, apply log + event mask, block-reduce
// Phase D: final 32-value reduce, write -sum/n
//
// No atomics anywhere -> bitwise deterministic. No device allocations
// (__device__ scratch only). All launches graph-capturable.

#define N_MAX    8192
#define BLOCK    256
#define IPT      8          // i's per thread in the pair kernel
#define JCH      256        // j's per chunk (== BLOCK so one staging pass)
#define JCHUNKS_MAX 32
#define EPS_F    1e-8f

__device__ float g_exp[N_MAX];
__device__ float g_part[JCHUNKS_MAX * N_MAX];   // [j_chunk][i]
__device__ float g_bsum[64];                    // per-block sums from finalize

// ---------------------------------------------------------------- Phase A
__global__ void cox_exp_kernel(const float* __restrict__ risk, int n) {
    int i = blockIdx.x * blockDim.x + threadIdx.x;
    if (i < n) g_exp[i] = expf(risk[i]);
}

// ---------------------------------------------------------------- Phase B
// Block (jc, it): accumulates, for each i in i-tile `it`, the sum of
// exp(theta_j) over j in chunk `jc` with t_j >= t_i. Writes the partial
// to g_part[jc*n + i].
__global__ __launch_bounds__(BLOCK) void cox_pair_kernel(
    const float* __restrict__ t, int n)
{
    __shared__ float ts[JCH];
    __shared__ float es[JCH];

    const int jc  = blockIdx.x;
    const int it  = blockIdx.y;
    const int tid = threadIdx.x;

    const int j0 = jc * JCH;
    ts[tid] = t[j0 + tid];
    es[tid] = g_exp[j0 + tid];
    __syncthreads();

    const int ibase = it * (BLOCK * IPT);

    float ti[IPT];
    float s[IPT];
#pragma unroll
    for (int k = 0; k < IPT; k++) {
        ti[k] = t[ibase + k * BLOCK + tid];   // coalesced
        s[k]  = 0.0f;
    }

#pragma unroll 4
    for (int j = 0; j < JCH; j++) {
        const float tj = ts[j];   // broadcast LDS
        const float ej = es[j];   // broadcast LDS
#pragma unroll
        for (int k = 0; k < IPT; k++) {
            if (tj >= ti[k]) s[k] += ej;   // FSETP + @P FADD
        }
    }

#pragma unroll
    for (int k = 0; k < IPT; k++) {
        g_part[jc * n + ibase + k * BLOCK + tid] = s[k];
    }
}

// ---------------------------------------------------------------- Phase C
// One thread per i: S_i = sum of partials (fixed order), contribution
// c_i = (theta_i - log(S_i + eps)) * e_i, then deterministic block reduce.
__global__ __launch_bounds__(BLOCK) void cox_finalize_kernel(
    const float* __restrict__ risk,
    const float* __restrict__ e,
    int n, int jchunks)
{
    const int i = blockIdx.x * blockDim.x + threadIdx.x;

    float S = 0.0f;
    for (int jc = 0; jc < jchunks; jc++) {
        S += g_part[jc * n + i];              // coalesced column reads
    }

    float c = (risk[i] - logf(S + EPS_F)) * e[i];

    __shared__ float red[BLOCK];
    red[threadIdx.x] = c;
    __syncthreads();

#pragma unroll
    for (int off = BLOCK / 2; off >= 64; off >>= 1) {
        if (threadIdx.x < off) red[threadIdx.x] += red[threadIdx.x + off];
        __syncthreads();
    }

    if (threadIdx.x < 32) {
        float v = red[threadIdx.x] + red[threadIdx.x + 32];
#pragma unroll
        for (int off = 16; off > 0; off >>= 1)
            v += __shfl_down_sync(0xffffffffu, v, off);
        if (threadIdx.x == 0) g_bsum[blockIdx.x] = v;
    }
}

// ---------------------------------------------------------------- Phase D
__global__ void cox_final_reduce(float* __restrict__ out, int n, int nblocks) {
    float v = (threadIdx.x < nblocks) ? g_bsum[threadIdx.x] : 0.0f;
#pragma unroll
    for (int off = 16; off > 0; off >>= 1)
        v += __shfl_down_sync(0xffffffffu, v, off);
    if (threadIdx.x == 0) out[0] = -v / (float)n;
}

// ---------------------------------------------------------------- launch
extern "C" void kernel_launch(void* const* d_in, const int* in_sizes, int n_in,
                              void* d_out, int out_size) {
    const float* risk = (const float*)d_in[0];
    const float* t    = (const float*)d_in[1];
    const float* e    = (const float*)d_in[2];
    float* out = (float*)d_out;

    const int n = in_sizes[0];            // 8192
    const int jchunks = n / JCH;          // 32
    const int itiles  = n / (BLOCK * IPT); // 4
    const int fblocks = n / BLOCK;        // 32

    cox_exp_kernel<<<(n + BLOCK - 1) / BLOCK, BLOCK>>>(risk, n);
    cox_pair_kernel<<<dim3(jchunks, itiles), BLOCK>>>(t, n);
    cox_finalize_kernel<<<fblocks, BLOCK>>>(risk, e, n, jchunks);
    cox_final_reduce<<<1, 32>>>(out, n, fblocks);
}